// round 14
// baseline (speedup 1.0000x reference)
#include <cuda_runtime.h>
#include <cuda_bf16.h>
#include <cstdint>

#define TT 512
#define BB 128
#define HH 512
#define G4 2048

typedef unsigned long long ull;

__device__ float g_xg[(size_t)TT * G4 * BB];   // [t][g][b]
__device__ float g_hs[(size_t)TT * BB * HH];   // [t][b][h]
__device__ float g_r[(size_t)BB * HH];
__device__ float g_e[(size_t)TT * BB];
__device__ unsigned g_flags[128 * 32];         // one padded slot per CTA

__device__ __forceinline__ ull fma2(ull a, ull b, ull c) {
    ull d; asm("fma.rn.f32x2 %0, %1, %2, %3;" : "=l"(d) : "l"(a), "l"(b), "l"(c)); return d;
}
__device__ __forceinline__ ull addf32x2(ull a, ull b) {
    ull d; asm("add.rn.f32x2 %0, %1, %2;" : "=l"(d) : "l"(a), "l"(b)); return d;
}
__device__ __forceinline__ ull pack2(float x, float y) {
    ull r; asm("mov.b64 %0, {%1, %2};" : "=l"(r) : "f"(x), "f"(y)); return r;
}
__device__ __forceinline__ float2 unpack2(ull v) {
    float2 f; asm("mov.b64 {%0, %1}, %2;" : "=f"(f.x), "=f"(f.y) : "l"(v)); return f;
}

__global__ void k_init(float* e) {
    int i = blockIdx.x * 256 + threadIdx.x;
    if (i < TT * BB) e[i] = 0.f;
    if (i < 128 * 32) g_flags[i] = 0u;
}

// no-op spacer for ncu capture-slot alignment
__global__ void k_nop() {}

// ---- xg[t][g][b] = x[b][t][:] @ W_ih[g][:] + bias[g].  tile: one t, 128 b x 128 g ----
__global__ __launch_bounds__(256, 2) void k_xg(
    const float* __restrict__ x, const float* __restrict__ Wih,
    const float* __restrict__ bih, const float* __restrict__ bhh,
    float* __restrict__ xg)
{
    __shared__ float As[2][8][132];
    __shared__ float Bs[2][8][132];
    extern __shared__ float slab[];   // 128*129
    const int tid = threadIdx.x;
    const int tx = tid & 15, ty = tid >> 4;
    const int tBlk = blockIdx.y, nBase = blockIdx.x * 128;
    const int lr = tid >> 1, lk = (tid & 1) * 4;
    const float* aptr = x + ((size_t)lr * TT + tBlk) * HH + lk;       // b = lr
    const float* bptr = Wih + (size_t)(nBase + lr) * HH + lk;

    ull acc[8][4];
#pragma unroll
    for (int i = 0; i < 8; i++)
#pragma unroll
        for (int j = 0; j < 4; j++) acc[i][j] = 0ull;

    {
        float4 av = *(const float4*)aptr;
        float4 bv = *(const float4*)bptr;
        As[0][lk+0][lr]=av.x; As[0][lk+1][lr]=av.y; As[0][lk+2][lr]=av.z; As[0][lk+3][lr]=av.w;
        Bs[0][lk+0][lr]=bv.x; Bs[0][lk+1][lr]=bv.y; Bs[0][lk+2][lr]=bv.z; Bs[0][lk+3][lr]=bv.w;
    }
    __syncthreads();
    int buf = 0;

    for (int k0 = 0; k0 < HH; k0 += 8) {
        const bool more = (k0 + 8) < HH;
        float4 av2, bv2;
        if (more) {
            av2 = *(const float4*)(aptr + k0 + 8);
            bv2 = *(const float4*)(bptr + k0 + 8);
        }
#pragma unroll
        for (int k = 0; k < 8; k++) {
            float4 a0 = *(const float4*)&As[buf][k][ty * 8];
            float4 a1 = *(const float4*)&As[buf][k][ty * 8 + 4];
            ulonglong2 b0 = *(const ulonglong2*)&Bs[buf][k][tx * 8];
            ulonglong2 b1 = *(const ulonglong2*)&Bs[buf][k][tx * 8 + 4];
            float af[8] = {a0.x, a0.y, a0.z, a0.w, a1.x, a1.y, a1.z, a1.w};
            ull bp[4] = {b0.x, b0.y, b1.x, b1.y};
#pragma unroll
            for (int i = 0; i < 8; i++) {
                ull ap = pack2(af[i], af[i]);
#pragma unroll
                for (int j = 0; j < 4; j++) acc[i][j] = fma2(ap, bp[j], acc[i][j]);
            }
        }
        if (more) {
            int nb = buf ^ 1;
            As[nb][lk+0][lr]=av2.x; As[nb][lk+1][lr]=av2.y; As[nb][lk+2][lr]=av2.z; As[nb][lk+3][lr]=av2.w;
            Bs[nb][lk+0][lr]=bv2.x; Bs[nb][lk+1][lr]=bv2.y; Bs[nb][lk+2][lr]=bv2.z; Bs[nb][lk+3][lr]=bv2.w;
        }
        __syncthreads();
        buf ^= 1;
    }

    // transpose epilogue -> slab[g_local][b]
    const int gc = nBase + tx * 8;
    float bias[8];
#pragma unroll
    for (int j = 0; j < 8; j++) bias[j] = bih[gc + j] + bhh[gc + j];
#pragma unroll
    for (int i = 0; i < 8; i++) {
        const int br = ty * 8 + i;
        float2 v0 = unpack2(acc[i][0]), v1 = unpack2(acc[i][1]);
        float2 v2 = unpack2(acc[i][2]), v3 = unpack2(acc[i][3]);
        slab[(tx*8+0)*129 + br] = v0.x + bias[0];
        slab[(tx*8+1)*129 + br] = v0.y + bias[1];
        slab[(tx*8+2)*129 + br] = v1.x + bias[2];
        slab[(tx*8+3)*129 + br] = v1.y + bias[3];
        slab[(tx*8+4)*129 + br] = v2.x + bias[4];
        slab[(tx*8+5)*129 + br] = v2.y + bias[5];
        slab[(tx*8+6)*129 + br] = v3.x + bias[6];
        slab[(tx*8+7)*129 + br] = v3.y + bias[7];
    }
    __syncthreads();
    float* obase = xg + ((size_t)tBlk * G4 + nBase) * BB;
    for (int i = tid; i < 128 * 32; i += 256) {
        int g = i >> 5, c4 = (i & 31) << 2;
        float4 v = make_float4(slab[g*129+c4], slab[g*129+c4+1], slab[g*129+c4+2], slab[g*129+c4+3]);
        *(float4*)(obase + (size_t)g * BB + c4) = v;
    }
}

// ---- persistent LSTM recurrence v3: lane = batch, NO shuffles ----
// 128 CTAs x 512 thr. CTA bx: cb = bx>>6 (64-batch half), cc = bx&63 (8 cols).
// Warp: rg = wid&7 -> col = cc*8+rg; bg = wid>>3 -> batches cb*64+bg*32+lane.
// Each lane serially accumulates its batch's 4 gate dot-products over all k.
// W column in SMEM, read via broadcast LDS.128; h staged in SMEM [b][516]
// (stride 516 floats => the 8 lanes per crossbar phase tile 128B: conflict-free).
__global__ __launch_bounds__(512, 1) void k_lstm(
    const float* __restrict__ Whh, const float* __restrict__ xg,
    float* __restrict__ hs)
{
    extern __shared__ float sm[];
    float* w_s = sm;                 // [8 cols][4 gates][512 k] = 16384 floats
    float* hb  = sm + 16384;         // [64][516]
    const int tid = threadIdx.x;
    const int bx = blockIdx.x;
    const int cb = bx >> 6;
    const int cc = bx & 63;
    const int wid = tid >> 5;
    const int lane = tid & 31;
    const int rg = wid & 7;
    const int bg = wid >> 3;
    const int col = cc * 8 + rg;
    const int bmine = cb * 64 + bg * 32 + lane;

    // load w_s[rg'][g][k] = Whh[(g*512 + cc*8 + rg')*512 + k]
    for (int i = tid; i < 4096; i += 512) {
        int idx = i * 4;
        int rgp = idx >> 11;
        int g = (idx >> 9) & 3;
        int k = idx & 511;
        *(float4*)&w_s[idx] = *(const float4*)&Whh[(size_t)(g * HH + cc * 8 + rgp) * HH + k];
    }

    float cst = 0.f;
    float xv[4];
#pragma unroll
    for (int g = 0; g < 4; g++)
        xv[g] = __ldcg(xg + (size_t)(g * HH + col) * BB + bmine);
    __syncthreads();

    unsigned* myflag = &g_flags[bx * 32];
    unsigned* pollflag = &g_flags[(tid & 127) * 32];
    const float* wp = w_s + rg * 2048;

    for (int t = 0; t < TT; t++) {
        float s[4] = {0.f, 0.f, 0.f, 0.f};

        if (t > 0) {
            // stage h(t-1) rows for our 64 batches
            const float* hsrc = hs + ((size_t)(t - 1) * BB + cb * 64) * HH;
            for (int i = tid; i < 8192; i += 512) {
                int bl = i >> 7, k4 = (i & 127) << 2;
                *(float4*)&hb[bl * 516 + k4] =
                    __ldcg((const float4*)(hsrc + (size_t)bl * HH + k4));
            }
            __syncthreads();

            const float* hrow = hb + (bg * 32 + lane) * 516;
            ull a0[4] = {0ull,0ull,0ull,0ull}, a1[4] = {0ull,0ull,0ull,0ull};
#pragma unroll 8
            for (int k = 0; k < 512; k += 4) {
                ulonglong2 hv = *(const ulonglong2*)(hrow + k);
#pragma unroll
                for (int g = 0; g < 4; g++) {
                    ulonglong2 wv = *(const ulonglong2*)(wp + g * 512 + k);
                    a0[g] = fma2(wv.x, hv.x, a0[g]);
                    a1[g] = fma2(wv.y, hv.y, a1[g]);
                }
            }
#pragma unroll
            for (int g = 0; g < 4; g++) {
                float2 p = unpack2(addf32x2(a0[g], a1[g]));
                s[g] = p.x + p.y;
            }
        }

        float gi = s[0] + xv[0];
        float gf = s[1] + xv[1];
        float gg = s[2] + xv[2];
        float go = s[3] + xv[3];
        float si = 1.f / (1.f + expf(-gi));
        float sf = 1.f / (1.f + expf(-gf));
        float so = 1.f / (1.f + expf(-go));
        cst = sf * cst + si * tanhf(gg);
        float h = so * tanhf(cst);
        __stcg(hs + ((size_t)t * BB + bmine) * HH + col, h);

        // prefetch next step's xg (independent of the recurrence)
        if (t + 1 < TT) {
            const float* xn = xg + (size_t)(t + 1) * G4 * BB;
#pragma unroll
            for (int g = 0; g < 4; g++)
                xv[g] = __ldcg(xn + (size_t)(g * HH + col) * BB + bmine);
        }

        // fence-free release/acquire grid barrier (also protects hb reuse)
        __syncthreads();
        if (tid == 0) {
            asm volatile("st.release.gpu.u32 [%0], %1;"
                         :: "l"(myflag), "r"((unsigned)(t + 1)) : "memory");
        }
        if (tid < 128) {
            unsigned v;
            do {
                asm volatile("ld.acquire.gpu.u32 %0, [%1];"
                             : "=r"(v) : "l"(pollflag) : "memory");
            } while (v < (unsigned)(t + 1));
        }
        __syncthreads();
    }
}

// ---- r[b][g] = h_last[b][:] @ U1[g][512:1024] ----
__global__ __launch_bounds__(256) void k_r(
    const float* __restrict__ hs, const float* __restrict__ U1, float* __restrict__ r)
{
    __shared__ float hl[512];
    const int b = blockIdx.x, tid = threadIdx.x;
    for (int i = tid; i < 512; i += 256)
        hl[i] = hs[((size_t)(TT - 1) * BB + b) * HH + i];
    __syncthreads();
    for (int g = tid; g < 512; g += 256) {
        const float* up = U1 + (size_t)g * 1024 + 512;
        float acc = 0.f;
        for (int k = 0; k < 512; k += 4) {
            float4 u = *(const float4*)(up + k);
            acc += hl[k] * u.x + hl[k+1] * u.y + hl[k+2] * u.z + hl[k+3] * u.w;
        }
        r[(size_t)b * HH + g] = acc;
    }
}

// ---- e[m] += sum_g tanh(hs@U1a + x@U2 + r) * Ve[g] ----
__global__ __launch_bounds__(256, 2) void k_e(
    const float* __restrict__ hs, const float* __restrict__ x,
    const float* __restrict__ U1, const float* __restrict__ U2,
    const float* __restrict__ r, const float* __restrict__ Ve,
    float* __restrict__ e)
{
    __shared__ float As[2][8][132];
    __shared__ float Bs[2][8][132];
    const int tid = threadIdx.x;
    const int tx = tid & 15, ty = tid >> 4;
    const int mBase = blockIdx.y * 128, nBase = blockIdx.x * 128;
    const int lr = tid >> 1, lk = (tid & 1) * 4;
    const int m = mBase + lr;
    const float* aptrs[2] = { hs + (size_t)m * HH + lk,
                              x + ((size_t)(m & 127) * TT + (m >> 7)) * HH + lk };
    const float* bptrs[2] = { U1 + (size_t)(nBase + lr) * 1024 + lk,
                              U2 + (size_t)(nBase + lr) * 512 + lk };

    ull acc[8][4];
#pragma unroll
    for (int i = 0; i < 8; i++)
#pragma unroll
        for (int j = 0; j < 4; j++) acc[i][j] = 0ull;

    {
        float4 av = *(const float4*)aptrs[0];
        float4 bv = *(const float4*)bptrs[0];
        As[0][lk+0][lr]=av.x; As[0][lk+1][lr]=av.y; As[0][lk+2][lr]=av.z; As[0][lk+3][lr]=av.w;
        Bs[0][lk+0][lr]=bv.x; Bs[0][lk+1][lr]=bv.y; Bs[0][lk+2][lr]=bv.z; Bs[0][lk+3][lr]=bv.w;
    }
    __syncthreads();
    int buf = 0;

    for (int ph = 0; ph < 2; ph++) {
        const float* ap = aptrs[ph];
        const float* bp_ = bptrs[ph];
        for (int k0 = 0; k0 < HH; k0 += 8) {
            const bool last = (ph == 1) && (k0 + 8 >= HH);
            float4 av2, bv2;
            if (!last) {
                const float* an = (k0 + 8 < HH) ? ap + k0 + 8 : aptrs[1];
                const float* bn = (k0 + 8 < HH) ? bp_ + k0 + 8 : bptrs[1];
                av2 = *(const float4*)an;
                bv2 = *(const float4*)bn;
            }
#pragma unroll
            for (int k = 0; k < 8; k++) {
                float4 a0 = *(const float4*)&As[buf][k][ty * 8];
                float4 a1 = *(const float4*)&As[buf][k][ty * 8 + 4];
                ulonglong2 b0 = *(const ulonglong2*)&Bs[buf][k][tx * 8];
                ulonglong2 b1 = *(const ulonglong2*)&Bs[buf][k][tx * 8 + 4];
                float af[8] = {a0.x, a0.y, a0.z, a0.w, a1.x, a1.y, a1.z, a1.w};
                ull bp2[4] = {b0.x, b0.y, b1.x, b1.y};
#pragma unroll
                for (int i = 0; i < 8; i++) {
                    ull apk = pack2(af[i], af[i]);
#pragma unroll
                    for (int j = 0; j < 4; j++) acc[i][j] = fma2(apk, bp2[j], acc[i][j]);
                }
            }
            if (!last) {
                int nb = buf ^ 1;
                As[nb][lk+0][lr]=av2.x; As[nb][lk+1][lr]=av2.y; As[nb][lk+2][lr]=av2.z; As[nb][lk+3][lr]=av2.w;
                Bs[nb][lk+0][lr]=bv2.x; Bs[nb][lk+1][lr]=bv2.y; Bs[nb][lk+2][lr]=bv2.z; Bs[nb][lk+3][lr]=bv2.w;
            }
            __syncthreads();
            buf ^= 1;
        }
    }

    const int gc = nBase + tx * 8;
    float ve[8];
#pragma unroll
    for (int j = 0; j < 8; j++) ve[j] = Ve[gc + j];
#pragma unroll
    for (int i = 0; i < 8; i++) {
        const int brow = ty * 8 + i;
        const float* rr = r + (size_t)brow * HH + gc;
        float si = 0.f; float2 v;
        v = unpack2(acc[i][0]); si += tanhf(v.x + rr[0]) * ve[0] + tanhf(v.y + rr[1]) * ve[1];
        v = unpack2(acc[i][1]); si += tanhf(v.x + rr[2]) * ve[2] + tanhf(v.y + rr[3]) * ve[3];
        v = unpack2(acc[i][2]); si += tanhf(v.x + rr[4]) * ve[4] + tanhf(v.y + rr[5]) * ve[5];
        v = unpack2(acc[i][3]); si += tanhf(v.x + rr[6]) * ve[6] + tanhf(v.y + rr[7]) * ve[7];
#pragma unroll
        for (int o = 8; o >= 1; o >>= 1)
            si += __shfl_xor_sync(0xffffffffu, si, o, 16);
        if (tx == 0) atomicAdd(&e[mBase + ty * 8 + i], si);
    }
}

// ---- softmax over t, context, output head; one CTA per batch element ----
__global__ __launch_bounds__(256) void k_final(
    const float* __restrict__ hs, const float* __restrict__ e,
    const float* __restrict__ Wout, const float* __restrict__ bout,
    float* __restrict__ out)
{
    __shared__ float al[512];
    __shared__ float red[256];
    const int b = blockIdx.x, tid = threadIdx.x;

    float ev0 = e[(size_t)tid * BB + b];
    float ev1 = e[(size_t)(tid + 256) * BB + b];

    red[tid] = fmaxf(ev0, ev1);
    __syncthreads();
    for (int s = 128; s > 0; s >>= 1) {
        if (tid < s) red[tid] = fmaxf(red[tid], red[tid + s]);
        __syncthreads();
    }
    float mx = red[0];
    __syncthreads();
    float x0 = expf(ev0 - mx), x1 = expf(ev1 - mx);
    red[tid] = x0 + x1;
    __syncthreads();
    for (int s = 128; s > 0; s >>= 1) {
        if (tid < s) red[tid] += red[tid + s];
        __syncthreads();
    }
    float inv = 1.f / red[0];
    al[tid] = x0 * inv;
    al[tid + 256] = x1 * inv;
    __syncthreads();

    float ctx0 = 0.f, ctx1 = 0.f;
    for (int t = 0; t < TT; t++) {
        float a = al[t];
        const float* hp = hs + ((size_t)t * BB + b) * HH;
        ctx0 += a * hp[tid];
        ctx1 += a * hp[tid + 256];
    }

    float p0 = ctx0 * Wout[tid] + ctx1 * Wout[tid + 256];
    float p1 = ctx0 * Wout[512 + tid] + ctx1 * Wout[512 + tid + 256];
    red[tid] = p0;
    __syncthreads();
    for (int s = 128; s > 0; s >>= 1) {
        if (tid < s) red[tid] += red[tid + s];
        __syncthreads();
    }
    float mu = red[0] + bout[0];
    __syncthreads();
    red[tid] = p1;
    __syncthreads();
    for (int s = 128; s > 0; s >>= 1) {
        if (tid < s) red[tid] += red[tid + s];
        __syncthreads();
    }
    if (tid == 0) {
        float pv = red[0] + bout[1];
        float sp = (pv > 20.f) ? pv : log1pf(expf(pv));
        out[b] = mu;
        out[BB + b] = sp + 1e-5f;
    }
}

extern "C" void kernel_launch(void* const* d_in, const int* in_sizes, int n_in,
                              void* d_out, int out_size) {
    const float* x    = (const float*)d_in[0];
    const float* Wih  = (const float*)d_in[1];
    const float* Whh  = (const float*)d_in[2];
    const float* bih  = (const float*)d_in[3];
    const float* bhh  = (const float*)d_in[4];
    const float* Ve   = (const float*)d_in[5];
    const float* U1   = (const float*)d_in[6];
    const float* U2   = (const float*)d_in[7];
    const float* Wout = (const float*)d_in[8];
    const float* bout = (const float*)d_in[9];
    float* out = (float*)d_out;

    float *xg, *hs, *r, *e;
    cudaGetSymbolAddress((void**)&xg, g_xg);
    cudaGetSymbolAddress((void**)&hs, g_hs);
    cudaGetSymbolAddress((void**)&r,  g_r);
    cudaGetSymbolAddress((void**)&e,  g_e);

    const int lstm_smem = (16384 + 64 * 516) * 4;   // 197632 B
    cudaFuncSetAttribute(k_xg,   cudaFuncAttributeMaxDynamicSharedMemorySize, 128 * 129 * 4);
    cudaFuncSetAttribute(k_lstm, cudaFuncAttributeMaxDynamicSharedMemorySize, lstm_smem);

    k_init<<<(TT * BB + 255) / 256, 256>>>(e);
    k_nop<<<1, 32>>>();   // spacers: put k_xg in ncu's capture slot (4th launch)
    k_nop<<<1, 32>>>();
    {
        dim3 g(G4 / 128, TT);
        k_xg<<<g, 256, 128 * 129 * 4>>>(x, Wih, bih, bhh, xg);
    }
    k_lstm<<<128, 512, lstm_smem>>>(Whh, xg, hs);
    k_r<<<BB, 256>>>(hs, U1, r);
    {
        dim3 g(HH / 128, (TT * BB) / 128);
        k_e<<<g, 256>>>(hs, x, U1, U2, r, Ve, e);
    }
    k_final<<<BB, 256>>>(hs, e, Wout, bout, out);
}

// round 16
// speedup vs baseline: 1.2882x; 1.2882x over previous
#include <cuda_runtime.h>
#include <cuda_bf16.h>
#include <cstdint>

#define TT 512
#define BB 128
#define HH 512
#define G4 2048

typedef unsigned long long ull;

__device__ float g_xg[(size_t)TT * G4 * BB];           // [t][g][b]
__device__ float g_hs[(size_t)TT * BB * HH];           // [t][b][h]
__device__ float g_r[(size_t)BB * HH];
__device__ float g_e[(size_t)TT * BB];
__device__ unsigned g_flags[128 * 32];
__device__ __nv_bfloat16 g_xh[(size_t)TT * BB * HH];   // [t][b][d]
__device__ __nv_bfloat16 g_xl[(size_t)TT * BB * HH];
__device__ __nv_bfloat16 g_wh[(size_t)G4 * HH];        // [g][d]
__device__ __nv_bfloat16 g_wl[(size_t)G4 * HH];

__device__ __forceinline__ ull fma2(ull a, ull b, ull c) {
    ull d; asm("fma.rn.f32x2 %0, %1, %2, %3;" : "=l"(d) : "l"(a), "l"(b), "l"(c)); return d;
}
__device__ __forceinline__ ull addf32x2(ull a, ull b) {
    ull d; asm("add.rn.f32x2 %0, %1, %2;" : "=l"(d) : "l"(a), "l"(b)); return d;
}
__device__ __forceinline__ ull pack2(float x, float y) {
    ull r; asm("mov.b64 %0, {%1, %2};" : "=l"(r) : "f"(x), "f"(y)); return r;
}
__device__ __forceinline__ float2 unpack2(ull v) {
    float2 f; asm("mov.b64 {%0, %1}, %2;" : "=f"(f.x), "=f"(f.y) : "l"(v)); return f;
}
__device__ __forceinline__ uint32_t smem_u32(const void* p) {
    return (uint32_t)__cvta_generic_to_shared(p);
}
__device__ __forceinline__ void ldsm_x4(uint32_t* r, uint32_t addr) {
    asm volatile("ldmatrix.sync.aligned.m8n8.x4.shared.b16 {%0,%1,%2,%3}, [%4];"
                 : "=r"(r[0]), "=r"(r[1]), "=r"(r[2]), "=r"(r[3]) : "r"(addr));
}
__device__ __forceinline__ void mma_bf16(float* d, const uint32_t* a, const uint32_t* b) {
    asm volatile("mma.sync.aligned.m16n8k16.row.col.f32.bf16.bf16.f32 "
                 "{%0,%1,%2,%3}, {%4,%5,%6,%7}, {%8,%9}, {%0,%1,%2,%3};"
                 : "+f"(d[0]), "+f"(d[1]), "+f"(d[2]), "+f"(d[3])
                 : "r"(a[0]), "r"(a[1]), "r"(a[2]), "r"(a[3]), "r"(b[0]), "r"(b[1]));
}

__global__ void k_init(float* e) {
    int i = blockIdx.x * 256 + threadIdx.x;
    if (i < TT * BB) e[i] = 0.f;
    if (i < 128 * 32) g_flags[i] = 0u;
}

// ---- split x (fp32 [b][t][d]) -> xh/xl (bf16 [t][b][d]) ----
__global__ __launch_bounds__(128) void k_split_x(
    const float* __restrict__ x, __nv_bfloat16* __restrict__ xh, __nv_bfloat16* __restrict__ xl)
{
    const int row = blockIdx.x;            // b*TT + t
    const int b = row >> 9, t = row & 511;
    const int d = threadIdx.x * 4;
    float4 v = *(const float4*)(x + (size_t)row * HH + d);
    float f[4] = {v.x, v.y, v.z, v.w};
    __nv_bfloat16 h[4], l[4];
#pragma unroll
    for (int i = 0; i < 4; i++) {
        h[i] = __float2bfloat16(f[i]);
        l[i] = __float2bfloat16(f[i] - __bfloat162float(h[i]));
    }
    size_t o = ((size_t)t * BB + b) * HH + d;
    *(__nv_bfloat162*)(xh + o)     = __nv_bfloat162(h[0], h[1]);
    *(__nv_bfloat162*)(xh + o + 2) = __nv_bfloat162(h[2], h[3]);
    *(__nv_bfloat162*)(xl + o)     = __nv_bfloat162(l[0], l[1]);
    *(__nv_bfloat162*)(xl + o + 2) = __nv_bfloat162(l[2], l[3]);
}

// ---- split W_ih -> wh/wl (bf16, same [g][d] layout) ----
__global__ __launch_bounds__(128) void k_split_w(
    const float* __restrict__ w, __nv_bfloat16* __restrict__ wh, __nv_bfloat16* __restrict__ wl)
{
    const int g = blockIdx.x;
    const int d = threadIdx.x * 4;
    float4 v = *(const float4*)(w + (size_t)g * HH + d);
    float f[4] = {v.x, v.y, v.z, v.w};
    __nv_bfloat16 h[4], l[4];
#pragma unroll
    for (int i = 0; i < 4; i++) {
        h[i] = __float2bfloat16(f[i]);
        l[i] = __float2bfloat16(f[i] - __bfloat162float(h[i]));
    }
    size_t o = (size_t)g * HH + d;
    *(__nv_bfloat162*)(wh + o)     = __nv_bfloat162(h[0], h[1]);
    *(__nv_bfloat162*)(wh + o + 2) = __nv_bfloat162(h[2], h[3]);
    *(__nv_bfloat162*)(wl + o)     = __nv_bfloat162(l[0], l[1]);
    *(__nv_bfloat162*)(wl + o + 2) = __nv_bfloat162(l[2], l[3]);
}

// ---- xg via split-bf16 tensor cores: xg[t][g][b] = x@W_ih^T + bias ----
// CTA: one t (128 b) x 128 g, K=512 in chunks of 64. 8 warps = 4(b) x 2(g),
// warp tile 32b x 64g. xg ~= xh@wh + xl@wh + xh@wl (xl@wl ~ 2^-18, dropped).
__global__ __launch_bounds__(256) void k_xg_mma(
    const __nv_bfloat16* __restrict__ xh, const __nv_bfloat16* __restrict__ xl,
    const __nv_bfloat16* __restrict__ wh, const __nv_bfloat16* __restrict__ wl,
    const float* __restrict__ bih, const float* __restrict__ bhh,
    float* __restrict__ xg)
{
    extern __shared__ char smraw[];
    __nv_bfloat16* Ah = (__nv_bfloat16*)smraw;   // [128][72]
    __nv_bfloat16* Al = Ah + 128 * 72;
    __nv_bfloat16* Bh = Al + 128 * 72;
    __nv_bfloat16* Bl = Bh + 128 * 72;
    float* slab = (float*)smraw;                  // aliased after mainloop: [128 g][132 b]

    const int tid = threadIdx.x;
    const int t = blockIdx.y, gBase = blockIdx.x * 128;
    const int wid = tid >> 5, lane = tid & 31;
    const int wb = wid >> 1, wg = wid & 1;

    const __nv_bfloat16* At = xh + (size_t)t * BB * HH;
    const __nv_bfloat16* At2 = xl + (size_t)t * BB * HH;
    const __nv_bfloat16* Bg = wh + (size_t)gBase * HH;
    const __nv_bfloat16* Bg2 = wl + (size_t)gBase * HH;

    float d[2][8][4];
#pragma unroll
    for (int m = 0; m < 2; m++)
#pragma unroll
        for (int n = 0; n < 8; n++)
#pragma unroll
            for (int q = 0; q < 4; q++) d[m][n][q] = 0.f;

    const int arow = wb * 32 + (lane & 15);
    const int akcol = (lane >> 4) * 8;
    const int brow = wg * 64 + ((lane >> 4) << 3) + (lane & 7);
    const int bkcol = ((lane >> 3) & 1) * 8;

    for (int k0 = 0; k0 < HH; k0 += 64) {
        __syncthreads();
        for (int i = tid; i < 1024; i += 256) {
            int r = i >> 3, c = (i & 7) * 8;
            *(uint4*)(Ah + r * 72 + c) = *(const uint4*)(At  + (size_t)r * HH + k0 + c);
            *(uint4*)(Al + r * 72 + c) = *(const uint4*)(At2 + (size_t)r * HH + k0 + c);
            *(uint4*)(Bh + r * 72 + c) = *(const uint4*)(Bg  + (size_t)r * HH + k0 + c);
            *(uint4*)(Bl + r * 72 + c) = *(const uint4*)(Bg2 + (size_t)r * HH + k0 + c);
        }
        __syncthreads();

#pragma unroll
        for (int kk = 0; kk < 64; kk += 16) {
            uint32_t ah[2][4], al[2][4];
            ldsm_x4(ah[0], smem_u32(Ah + (arow)      * 72 + kk + akcol));
            ldsm_x4(ah[1], smem_u32(Ah + (arow + 16) * 72 + kk + akcol));
            ldsm_x4(al[0], smem_u32(Al + (arow)      * 72 + kk + akcol));
            ldsm_x4(al[1], smem_u32(Al + (arow + 16) * 72 + kk + akcol));
#pragma unroll
            for (int np = 0; np < 4; np++) {
                uint32_t bh[4], bl[4];
                ldsm_x4(bh, smem_u32(Bh + (brow + np * 16) * 72 + kk + bkcol));
                ldsm_x4(bl, smem_u32(Bl + (brow + np * 16) * 72 + kk + bkcol));
#pragma unroll
                for (int m = 0; m < 2; m++) {
                    mma_bf16(d[m][np * 2 + 0], ah[m], bh + 0);
                    mma_bf16(d[m][np * 2 + 0], al[m], bh + 0);
                    mma_bf16(d[m][np * 2 + 0], ah[m], bl + 0);
                    mma_bf16(d[m][np * 2 + 1], ah[m], bh + 2);
                    mma_bf16(d[m][np * 2 + 1], al[m], bh + 2);
                    mma_bf16(d[m][np * 2 + 1], ah[m], bl + 2);
                }
            }
        }
    }
    __syncthreads();

    // frags -> slab[g][b]
#pragma unroll
    for (int m = 0; m < 2; m++)
#pragma unroll
        for (int n = 0; n < 8; n++) {
            int b = wb * 32 + m * 16 + (lane >> 2);
            int g = wg * 64 + n * 8 + (lane & 3) * 2;
            slab[g * 132 + b]           = d[m][n][0];
            slab[(g + 1) * 132 + b]     = d[m][n][1];
            slab[g * 132 + b + 8]       = d[m][n][2];
            slab[(g + 1) * 132 + b + 8] = d[m][n][3];
        }
    __syncthreads();

    float* obase = xg + ((size_t)t * G4 + gBase) * BB;
    for (int i = tid; i < 4096; i += 256) {
        int g = i >> 5, b4 = (i & 31) * 4;
        float bias = bih[gBase + g] + bhh[gBase + g];
        float4 v = *(float4*)&slab[g * 132 + b4];
        v.x += bias; v.y += bias; v.z += bias; v.w += bias;
        *(float4*)(obase + (size_t)g * BB + b4) = v;
    }
}

// ---- persistent LSTM recurrence v2 (register W_hh + butterfly) — known-good ----
__global__ __launch_bounds__(512, 1) void k_lstm(
    const float* __restrict__ Whh, const float* __restrict__ xg,
    float* __restrict__ hs)
{
    extern __shared__ float hb[];   // 64 x 516 floats
    const int tid = threadIdx.x;
    const int bx = blockIdx.x;
    const int cb = bx >> 6;
    const int cc = bx & 63;
    const int wid = tid >> 5;
    const int lane = tid & 31;
    const int rg = wid & 7;
    const int bg = wid >> 3;
    const int col = cc * 8 + rg;
    const int bmine = cb * 64 + bg * 32 + lane;

    ull wlo[4][4], whi[4][4];
#pragma unroll
    for (int g = 0; g < 4; g++) {
        const float* wp = Whh + (size_t)(g * HH + col) * HH + 4 * lane;
#pragma unroll
        for (int c = 0; c < 4; c++) {
            float4 wv = *(const float4*)(wp + 128 * c);
            wlo[g][c] = pack2(wv.x, wv.y);
            whi[g][c] = pack2(wv.z, wv.w);
        }
    }

    float cst = 0.f;
    float xv[4];
#pragma unroll
    for (int g = 0; g < 4; g++)
        xv[g] = __ldcg(xg + (size_t)(g * HH + col) * BB + bmine);

    unsigned* myflag = &g_flags[bx * 32];
    unsigned* pollflag = &g_flags[(tid & 127) * 32];

    for (int t = 0; t < TT; t++) {
        ull g01 = 0ull, g23 = 0ull;

        if (t > 0) {
            const float* hsrc = hs + ((size_t)(t - 1) * BB + cb * 64) * HH;
            for (int i = tid; i < 64 * 128; i += 512) {
                int bl = i >> 7, k4 = (i & 127) << 2;
                *(float4*)&hb[bl * 516 + k4] =
                    __ldcg((const float4*)(hsrc + (size_t)bl * HH + k4));
            }
            __syncthreads();

            for (int it = 0; it < 32; it++) {
                const float* hrow = hb + (bg * 32 + it) * 516 + 4 * lane;
                ull a0[4] = {0ull,0ull,0ull,0ull}, a1[4] = {0ull,0ull,0ull,0ull};
#pragma unroll
                for (int c = 0; c < 4; c++) {
                    ulonglong2 hv = *(const ulonglong2*)(hrow + 128 * c);
#pragma unroll
                    for (int g = 0; g < 4; g++) {
                        a0[g] = fma2(wlo[g][c], hv.x, a0[g]);
                        a1[g] = fma2(whi[g][c], hv.y, a1[g]);
                    }
                }
                float s[4];
#pragma unroll
                for (int g = 0; g < 4; g++) {
                    float2 p = unpack2(addf32x2(a0[g], a1[g]));
                    s[g] = p.x + p.y;
                }
                ull p01 = pack2(s[0], s[1]);
                ull p23 = pack2(s[2], s[3]);
#pragma unroll
                for (int off = 16; off >= 1; off >>= 1) {
                    p01 = addf32x2(p01, __shfl_xor_sync(0xffffffffu, p01, off));
                    p23 = addf32x2(p23, __shfl_xor_sync(0xffffffffu, p23, off));
                }
                if (lane == it) { g01 = p01; g23 = p23; }
            }
        }

        float2 q0 = unpack2(g01), q1 = unpack2(g23);
        float gi = q0.x + xv[0];
        float gf = q0.y + xv[1];
        float gg = q1.x + xv[2];
        float go = q1.y + xv[3];
        float si = 1.f / (1.f + expf(-gi));
        float sf = 1.f / (1.f + expf(-gf));
        float so = 1.f / (1.f + expf(-go));
        cst = sf * cst + si * tanhf(gg);
        float h = so * tanhf(cst);
        __stcg(hs + ((size_t)t * BB + bmine) * HH + col, h);

        if (t + 1 < TT) {
            const float* xn = xg + (size_t)(t + 1) * G4 * BB;
#pragma unroll
            for (int g = 0; g < 4; g++)
                xv[g] = __ldcg(xn + (size_t)(g * HH + col) * BB + bmine);
        }

        __syncthreads();
        if (tid == 0) {
            asm volatile("st.release.gpu.u32 [%0], %1;"
                         :: "l"(myflag), "r"((unsigned)(t + 1)) : "memory");
        }
        if (tid < 128) {
            unsigned v;
            do {
                asm volatile("ld.acquire.gpu.u32 %0, [%1];"
                             : "=r"(v) : "l"(pollflag) : "memory");
            } while (v < (unsigned)(t + 1));
        }
        __syncthreads();
    }
}

// ---- r[b][g] = h_last[b][:] @ U1[g][512:1024] ----
__global__ __launch_bounds__(256) void k_r(
    const float* __restrict__ hs, const float* __restrict__ U1, float* __restrict__ r)
{
    __shared__ float hl[512];
    const int b = blockIdx.x, tid = threadIdx.x;
    for (int i = tid; i < 512; i += 256)
        hl[i] = hs[((size_t)(TT - 1) * BB + b) * HH + i];
    __syncthreads();
    for (int g = tid; g < 512; g += 256) {
        const float* up = U1 + (size_t)g * 1024 + 512;
        float acc = 0.f;
        for (int k = 0; k < 512; k += 4) {
            float4 u = *(const float4*)(up + k);
            acc += hl[k] * u.x + hl[k+1] * u.y + hl[k+2] * u.z + hl[k+3] * u.w;
        }
        r[(size_t)b * HH + g] = acc;
    }
}

// ---- e[m] += sum_g tanh(hs@U1a + x@U2 + r) * Ve[g] ----
__global__ __launch_bounds__(256, 2) void k_e(
    const float* __restrict__ hs, const float* __restrict__ x,
    const float* __restrict__ U1, const float* __restrict__ U2,
    const float* __restrict__ r, const float* __restrict__ Ve,
    float* __restrict__ e)
{
    __shared__ float As[2][8][132];
    __shared__ float Bs[2][8][132];
    const int tid = threadIdx.x;
    const int tx = tid & 15, ty = tid >> 4;
    const int mBase = blockIdx.y * 128, nBase = blockIdx.x * 128;
    const int lr = tid >> 1, lk = (tid & 1) * 4;
    const int m = mBase + lr;
    const float* aptrs[2] = { hs + (size_t)m * HH + lk,
                              x + ((size_t)(m & 127) * TT + (m >> 7)) * HH + lk };
    const float* bptrs[2] = { U1 + (size_t)(nBase + lr) * 1024 + lk,
                              U2 + (size_t)(nBase + lr) * 512 + lk };

    ull acc[8][4];
#pragma unroll
    for (int i = 0; i < 8; i++)
#pragma unroll
        for (int j = 0; j < 4; j++) acc[i][j] = 0ull;

    {
        float4 av = *(const float4*)aptrs[0];
        float4 bv = *(const float4*)bptrs[0];
        As[0][lk+0][lr]=av.x; As[0][lk+1][lr]=av.y; As[0][lk+2][lr]=av.z; As[0][lk+3][lr]=av.w;
        Bs[0][lk+0][lr]=bv.x; Bs[0][lk+1][lr]=bv.y; Bs[0][lk+2][lr]=bv.z; Bs[0][lk+3][lr]=bv.w;
    }
    __syncthreads();
    int buf = 0;

    for (int ph = 0; ph < 2; ph++) {
        const float* ap = aptrs[ph];
        const float* bp_ = bptrs[ph];
        for (int k0 = 0; k0 < HH; k0 += 8) {
            const bool last = (ph == 1) && (k0 + 8 >= HH);
            float4 av2, bv2;
            if (!last) {
                const float* an = (k0 + 8 < HH) ? ap + k0 + 8 : aptrs[1];
                const float* bn = (k0 + 8 < HH) ? bp_ + k0 + 8 : bptrs[1];
                av2 = *(const float4*)an;
                bv2 = *(const float4*)bn;
            }
#pragma unroll
            for (int k = 0; k < 8; k++) {
                float4 a0 = *(const float4*)&As[buf][k][ty * 8];
                float4 a1 = *(const float4*)&As[buf][k][ty * 8 + 4];
                ulonglong2 b0 = *(const ulonglong2*)&Bs[buf][k][tx * 8];
                ulonglong2 b1 = *(const ulonglong2*)&Bs[buf][k][tx * 8 + 4];
                float af[8] = {a0.x, a0.y, a0.z, a0.w, a1.x, a1.y, a1.z, a1.w};
                ull bp2[4] = {b0.x, b0.y, b1.x, b1.y};
#pragma unroll
                for (int i = 0; i < 8; i++) {
                    ull apk = pack2(af[i], af[i]);
#pragma unroll
                    for (int j = 0; j < 4; j++) acc[i][j] = fma2(apk, bp2[j], acc[i][j]);
                }
            }
            if (!last) {
                int nb = buf ^ 1;
                As[nb][lk+0][lr]=av2.x; As[nb][lk+1][lr]=av2.y; As[nb][lk+2][lr]=av2.z; As[nb][lk+3][lr]=av2.w;
                Bs[nb][lk+0][lr]=bv2.x; Bs[nb][lk+1][lr]=bv2.y; Bs[nb][lk+2][lr]=bv2.z; Bs[nb][lk+3][lr]=bv2.w;
            }
            __syncthreads();
            buf ^= 1;
        }
    }

    const int gc = nBase + tx * 8;
    float ve[8];
#pragma unroll
    for (int j = 0; j < 8; j++) ve[j] = Ve[gc + j];
#pragma unroll
    for (int i = 0; i < 8; i++) {
        const int brow = ty * 8 + i;
        const float* rr = r + (size_t)brow * HH + gc;
        float si = 0.f; float2 v;
        v = unpack2(acc[i][0]); si += tanhf(v.x + rr[0]) * ve[0] + tanhf(v.y + rr[1]) * ve[1];
        v = unpack2(acc[i][1]); si += tanhf(v.x + rr[2]) * ve[2] + tanhf(v.y + rr[3]) * ve[3];
        v = unpack2(acc[i][2]); si += tanhf(v.x + rr[4]) * ve[4] + tanhf(v.y + rr[5]) * ve[5];
        v = unpack2(acc[i][3]); si += tanhf(v.x + rr[6]) * ve[6] + tanhf(v.y + rr[7]) * ve[7];
#pragma unroll
        for (int o = 8; o >= 1; o >>= 1)
            si += __shfl_xor_sync(0xffffffffu, si, o, 16);
        if (tx == 0) atomicAdd(&e[mBase + ty * 8 + i], si);
    }
}

// ---- softmax over t, context, output head ----
__global__ __launch_bounds__(256) void k_final(
    const float* __restrict__ hs, const float* __restrict__ e,
    const float* __restrict__ Wout, const float* __restrict__ bout,
    float* __restrict__ out)
{
    __shared__ float al[512];
    __shared__ float red[256];
    const int b = blockIdx.x, tid = threadIdx.x;

    float ev0 = e[(size_t)tid * BB + b];
    float ev1 = e[(size_t)(tid + 256) * BB + b];

    red[tid] = fmaxf(ev0, ev1);
    __syncthreads();
    for (int s = 128; s > 0; s >>= 1) {
        if (tid < s) red[tid] = fmaxf(red[tid], red[tid + s]);
        __syncthreads();
    }
    float mx = red[0];
    __syncthreads();
    float x0 = expf(ev0 - mx), x1 = expf(ev1 - mx);
    red[tid] = x0 + x1;
    __syncthreads();
    for (int s = 128; s > 0; s >>= 1) {
        if (tid < s) red[tid] += red[tid + s];
        __syncthreads();
    }
    float inv = 1.f / red[0];
    al[tid] = x0 * inv;
    al[tid + 256] = x1 * inv;
    __syncthreads();

    float ctx0 = 0.f, ctx1 = 0.f;
    for (int t = 0; t < TT; t++) {
        float a = al[t];
        const float* hp = hs + ((size_t)t * BB + b) * HH;
        ctx0 += a * hp[tid];
        ctx1 += a * hp[tid + 256];
    }

    float p0 = ctx0 * Wout[tid] + ctx1 * Wout[tid + 256];
    float p1 = ctx0 * Wout[512 + tid] + ctx1 * Wout[512 + tid + 256];
    red[tid] = p0;
    __syncthreads();
    for (int s = 128; s > 0; s >>= 1) {
        if (tid < s) red[tid] += red[tid + s];
        __syncthreads();
    }
    float mu = red[0] + bout[0];
    __syncthreads();
    red[tid] = p1;
    __syncthreads();
    for (int s = 128; s > 0; s >>= 1) {
        if (tid < s) red[tid] += red[tid + s];
        __syncthreads();
    }
    if (tid == 0) {
        float pv = red[0] + bout[1];
        float sp = (pv > 20.f) ? pv : log1pf(expf(pv));
        out[b] = mu;
        out[BB + b] = sp + 1e-5f;
    }
}

extern "C" void kernel_launch(void* const* d_in, const int* in_sizes, int n_in,
                              void* d_out, int out_size) {
    const float* x    = (const float*)d_in[0];
    const float* Wih  = (const float*)d_in[1];
    const float* Whh  = (const float*)d_in[2];
    const float* bih  = (const float*)d_in[3];
    const float* bhh  = (const float*)d_in[4];
    const float* Ve   = (const float*)d_in[5];
    const float* U1   = (const float*)d_in[6];
    const float* U2   = (const float*)d_in[7];
    const float* Wout = (const float*)d_in[8];
    const float* bout = (const float*)d_in[9];
    float* out = (float*)d_out;

    float *xg, *hs, *r, *e;
    __nv_bfloat16 *xh, *xl, *wh, *wl;
    cudaGetSymbolAddress((void**)&xg, g_xg);
    cudaGetSymbolAddress((void**)&hs, g_hs);
    cudaGetSymbolAddress((void**)&r,  g_r);
    cudaGetSymbolAddress((void**)&e,  g_e);
    cudaGetSymbolAddress((void**)&xh, g_xh);
    cudaGetSymbolAddress((void**)&xl, g_xl);
    cudaGetSymbolAddress((void**)&wh, g_wh);
    cudaGetSymbolAddress((void**)&wl, g_wl);

    const int lstm_smem = 64 * 516 * 4;          // 132096 B
    const int xg_smem = 4 * 128 * 72 * 2;        // 73728 B
    cudaFuncSetAttribute(k_xg_mma, cudaFuncAttributeMaxDynamicSharedMemorySize, xg_smem);
    cudaFuncSetAttribute(k_lstm,   cudaFuncAttributeMaxDynamicSharedMemorySize, lstm_smem);

    k_init<<<(TT * BB + 255) / 256, 256>>>(e);
    k_split_x<<<BB * TT, 128>>>(x, xh, xl);
    k_split_w<<<G4, 128>>>(Wih, wh, wl);
    {
        dim3 g(G4 / 128, TT);
        k_xg_mma<<<g, 256, xg_smem>>>(xh, xl, wh, wl, bih, bhh, xg);
    }
    k_lstm<<<128, 512, lstm_smem>>>(Whh, xg, hs);
    k_r<<<BB, 256>>>(hs, U1, r);
    {
        dim3 g(HH / 128, (TT * BB) / 128);
        k_e<<<g, 256>>>(hs, x, U1, U2, r, Ve, e);
    }
    k_final<<<BB, 256>>>(hs, e, Wout, bout, out);
}

// round 17
// speedup vs baseline: 1.4557x; 1.1301x over previous
#include <cuda_runtime.h>
#include <cuda_bf16.h>
#include <cstdint>

#define TT 512
#define BB 128
#define HH 512
#define G4 2048

typedef unsigned long long ull;

__device__ float g_xg[(size_t)TT * G4 * BB];           // [t][g][b]
__device__ float g_hs[(size_t)TT * BB * HH];           // [t][b][h]
__device__ float g_r[(size_t)BB * HH];
__device__ float g_e[(size_t)TT * BB];
__device__ unsigned g_flags[128 * 32];
__device__ __nv_bfloat16 g_xh[(size_t)TT * BB * HH];   // [t][b][d]
__device__ __nv_bfloat16 g_xl[(size_t)TT * BB * HH];
__device__ __nv_bfloat16 g_wh[(size_t)G4 * HH];        // [g][d]
__device__ __nv_bfloat16 g_wl[(size_t)G4 * HH];

__device__ __forceinline__ ull fma2(ull a, ull b, ull c) {
    ull d; asm("fma.rn.f32x2 %0, %1, %2, %3;" : "=l"(d) : "l"(a), "l"(b), "l"(c)); return d;
}
__device__ __forceinline__ ull pack2(float x, float y) {
    ull r; asm("mov.b64 %0, {%1, %2};" : "=l"(r) : "f"(x), "f"(y)); return r;
}
__device__ __forceinline__ float2 unpack2(ull v) {
    float2 f; asm("mov.b64 {%0, %1}, %2;" : "=f"(f.x), "=f"(f.y) : "l"(v)); return f;
}
__device__ __forceinline__ uint32_t smem_u32(const void* p) {
    return (uint32_t)__cvta_generic_to_shared(p);
}
__device__ __forceinline__ void ldsm_x4(uint32_t* r, uint32_t addr) {
    asm volatile("ldmatrix.sync.aligned.m8n8.x4.shared.b16 {%0,%1,%2,%3}, [%4];"
                 : "=r"(r[0]), "=r"(r[1]), "=r"(r[2]), "=r"(r[3]) : "r"(addr));
}
__device__ __forceinline__ void mma_bf16(float* d, const uint32_t* a, const uint32_t* b) {
    asm volatile("mma.sync.aligned.m16n8k16.row.col.f32.bf16.bf16.f32 "
                 "{%0,%1,%2,%3}, {%4,%5,%6,%7}, {%8,%9}, {%0,%1,%2,%3};"
                 : "+f"(d[0]), "+f"(d[1]), "+f"(d[2]), "+f"(d[3])
                 : "r"(a[0]), "r"(a[1]), "r"(a[2]), "r"(a[3]), "r"(b[0]), "r"(b[1]));
}
__device__ __forceinline__ void split4(float4 v, __nv_bfloat162& h0, __nv_bfloat162& h1,
                                       __nv_bfloat162& l0, __nv_bfloat162& l1) {
    h0 = __float22bfloat162_rn(make_float2(v.x, v.y));
    h1 = __float22bfloat162_rn(make_float2(v.z, v.w));
    float2 f0 = __bfloat1622float2(h0), f1 = __bfloat1622float2(h1);
    l0 = __float22bfloat162_rn(make_float2(v.x - f0.x, v.y - f0.y));
    l1 = __float22bfloat162_rn(make_float2(v.z - f1.x, v.w - f1.y));
}

__global__ void k_init(float* e) {
    int i = blockIdx.x * 256 + threadIdx.x;
    if (i < TT * BB) e[i] = 0.f;
    if (i < 128 * 32) g_flags[i] = 0u;
}

// ---- merged split: x (fp32 [b][t][d]) -> xh/xl [t][b][d]; W_ih -> wh/wl ----
__global__ __launch_bounds__(128) void k_split(
    const float* __restrict__ x, const float* __restrict__ Wih,
    __nv_bfloat16* __restrict__ xh, __nv_bfloat16* __restrict__ xl,
    __nv_bfloat16* __restrict__ wh, __nv_bfloat16* __restrict__ wl)
{
    const int blk = blockIdx.x;
    const int d = threadIdx.x * 4;
    __nv_bfloat162 h0, h1, l0, l1;
    if (blk < BB * TT) {
        const int b = blk >> 9, t = blk & 511;
        float4 v = *(const float4*)(x + (size_t)blk * HH + d);
        split4(v, h0, h1, l0, l1);
        size_t o = ((size_t)t * BB + b) * HH + d;
        *(__nv_bfloat162*)(xh + o) = h0;     *(__nv_bfloat162*)(xh + o + 2) = h1;
        *(__nv_bfloat162*)(xl + o) = l0;     *(__nv_bfloat162*)(xl + o + 2) = l1;
    } else {
        const int g = blk - BB * TT;
        float4 v = *(const float4*)(Wih + (size_t)g * HH + d);
        split4(v, h0, h1, l0, l1);
        size_t o = (size_t)g * HH + d;
        *(__nv_bfloat162*)(wh + o) = h0;     *(__nv_bfloat162*)(wh + o + 2) = h1;
        *(__nv_bfloat162*)(wl + o) = l0;     *(__nv_bfloat162*)(wl + o + 2) = l1;
    }
}

// ---- xg via split-bf16 tensor cores (unchanged from R16) ----
__global__ __launch_bounds__(256) void k_xg_mma(
    const __nv_bfloat16* __restrict__ xh, const __nv_bfloat16* __restrict__ xl,
    const __nv_bfloat16* __restrict__ wh, const __nv_bfloat16* __restrict__ wl,
    const float* __restrict__ bih, const float* __restrict__ bhh,
    float* __restrict__ xg)
{
    extern __shared__ char smraw[];
    __nv_bfloat16* Ah = (__nv_bfloat16*)smraw;   // [128][72]
    __nv_bfloat16* Al = Ah + 128 * 72;
    __nv_bfloat16* Bh = Al + 128 * 72;
    __nv_bfloat16* Bl = Bh + 128 * 72;
    float* slab = (float*)smraw;

    const int tid = threadIdx.x;
    const int t = blockIdx.y, gBase = blockIdx.x * 128;
    const int wid = tid >> 5, lane = tid & 31;
    const int wb = wid >> 1, wg = wid & 1;

    const __nv_bfloat16* At = xh + (size_t)t * BB * HH;
    const __nv_bfloat16* At2 = xl + (size_t)t * BB * HH;
    const __nv_bfloat16* Bg = wh + (size_t)gBase * HH;
    const __nv_bfloat16* Bg2 = wl + (size_t)gBase * HH;

    float d[2][8][4];
#pragma unroll
    for (int m = 0; m < 2; m++)
#pragma unroll
        for (int n = 0; n < 8; n++)
#pragma unroll
            for (int q = 0; q < 4; q++) d[m][n][q] = 0.f;

    const int arow = wb * 32 + (lane & 15);
    const int akcol = (lane >> 4) * 8;
    const int brow = wg * 64 + ((lane >> 4) << 3) + (lane & 7);
    const int bkcol = ((lane >> 3) & 1) * 8;

    for (int k0 = 0; k0 < HH; k0 += 64) {
        __syncthreads();
        for (int i = tid; i < 1024; i += 256) {
            int r = i >> 3, c = (i & 7) * 8;
            *(uint4*)(Ah + r * 72 + c) = *(const uint4*)(At  + (size_t)r * HH + k0 + c);
            *(uint4*)(Al + r * 72 + c) = *(const uint4*)(At2 + (size_t)r * HH + k0 + c);
            *(uint4*)(Bh + r * 72 + c) = *(const uint4*)(Bg  + (size_t)r * HH + k0 + c);
            *(uint4*)(Bl + r * 72 + c) = *(const uint4*)(Bg2 + (size_t)r * HH + k0 + c);
        }
        __syncthreads();

#pragma unroll
        for (int kk = 0; kk < 64; kk += 16) {
            uint32_t ah[2][4], al[2][4];
            ldsm_x4(ah[0], smem_u32(Ah + (arow)      * 72 + kk + akcol));
            ldsm_x4(ah[1], smem_u32(Ah + (arow + 16) * 72 + kk + akcol));
            ldsm_x4(al[0], smem_u32(Al + (arow)      * 72 + kk + akcol));
            ldsm_x4(al[1], smem_u32(Al + (arow + 16) * 72 + kk + akcol));
#pragma unroll
            for (int np = 0; np < 4; np++) {
                uint32_t bh[4], bl[4];
                ldsm_x4(bh, smem_u32(Bh + (brow + np * 16) * 72 + kk + bkcol));
                ldsm_x4(bl, smem_u32(Bl + (brow + np * 16) * 72 + kk + bkcol));
#pragma unroll
                for (int m = 0; m < 2; m++) {
                    mma_bf16(d[m][np * 2 + 0], ah[m], bh + 0);
                    mma_bf16(d[m][np * 2 + 0], al[m], bh + 0);
                    mma_bf16(d[m][np * 2 + 0], ah[m], bl + 0);
                    mma_bf16(d[m][np * 2 + 1], ah[m], bh + 2);
                    mma_bf16(d[m][np * 2 + 1], al[m], bh + 2);
                    mma_bf16(d[m][np * 2 + 1], ah[m], bl + 2);
                }
            }
        }
    }
    __syncthreads();

#pragma unroll
    for (int m = 0; m < 2; m++)
#pragma unroll
        for (int n = 0; n < 8; n++) {
            int b = wb * 32 + m * 16 + (lane >> 2);
            int g = wg * 64 + n * 8 + (lane & 3) * 2;
            slab[g * 132 + b]           = d[m][n][0];
            slab[(g + 1) * 132 + b]     = d[m][n][1];
            slab[g * 132 + b + 8]       = d[m][n][2];
            slab[(g + 1) * 132 + b + 8] = d[m][n][3];
        }
    __syncthreads();

    float* obase = xg + ((size_t)t * G4 + gBase) * BB;
    for (int i = tid; i < 4096; i += 256) {
        int g = i >> 5, b4 = (i & 31) * 4;
        float bias = bih[gBase + g] + bhh[gBase + g];
        float4 v = *(float4*)&slab[g * 132 + b4];
        v.x += bias; v.y += bias; v.z += bias; v.w += bias;
        *(float4*)(obase + (size_t)g * BB + b4) = v;
    }
}

// ---- persistent LSTM recurrence v4: split-bf16 tensor-core GEMM per step ----
// 128 CTAs x 128 thr. CTA bx: cb = bx&1 (64-batch half), gg = bx>>1 (8 h-cols).
// B tile rows ordered n = gate*8 + col_local so each thread's 4 D-fragments
// hold complete (i,f,g,o) quads for its 4 (b,col) states; c stays in registers.
// W (32x512) split to SMEM once; h(t-1) staged+split to SMEM each step.
__global__ __launch_bounds__(128, 1) void k_lstm_mma(
    const float* __restrict__ Whh, const float* __restrict__ xg,
    float* __restrict__ hs)
{
    extern __shared__ char smr[];
    __nv_bfloat16* Hhi = (__nv_bfloat16*)smr;        // [64][520]
    __nv_bfloat16* Hlo = Hhi + 64 * 520;
    __nv_bfloat16* Whi = Hlo + 64 * 520;             // [32][520], n = gate*8+col
    __nv_bfloat16* Wlo = Whi + 32 * 520;

    const int tid = threadIdx.x;
    const int bx = blockIdx.x;
    const int cb = bx & 1;
    const int gg = bx >> 1;
    const int wm = tid >> 5;        // warp = m-tile (16 batches)
    const int lane = tid & 31;

    // one-time: split W rows into SMEM
    for (int i = tid; i < 32 * 128; i += 128) {
        int n = i >> 7, c4 = (i & 127) * 4;
        int row = (n >> 3) * HH + gg * 8 + (n & 7);
        float4 v = *(const float4*)(Whh + (size_t)row * HH + c4);
        __nv_bfloat162 h0, h1, l0, l1;
        split4(v, h0, h1, l0, l1);
        *(__nv_bfloat162*)(Whi + n * 520 + c4) = h0;
        *(__nv_bfloat162*)(Whi + n * 520 + c4 + 2) = h1;
        *(__nv_bfloat162*)(Wlo + n * 520 + c4) = l0;
        *(__nv_bfloat162*)(Wlo + n * 520 + c4 + 2) = l1;
    }

    // this thread's 4 states: s -> b = r0 + (s>>1)*8, col = c0 + (s&1)
    const int r0 = cb * 64 + wm * 16 + (lane >> 2);
    const int c0 = gg * 8 + (lane & 3) * 2;
    float cst[4] = {0.f, 0.f, 0.f, 0.f};

    float xv[4][4];   // [state][gate]
    {
        const float* xb = xg;
#pragma unroll
        for (int s = 0; s < 4; s++) {
            int b = r0 + (s >> 1) * 8, col = c0 + (s & 1);
#pragma unroll
            for (int g = 0; g < 4; g++)
                xv[s][g] = __ldcg(xb + (size_t)(g * HH + col) * BB + b);
        }
    }

    // ldmatrix byte-address bases (row pad 520 elems = 1040B -> conflict-free)
    const uint32_t a_hi = smem_u32(Hhi + ((wm * 16 + (lane & 15)) * 520 + (lane >> 4) * 8));
    const uint32_t a_lo = smem_u32(Hlo + ((wm * 16 + (lane & 15)) * 520 + (lane >> 4) * 8));
    const int bnr = ((lane >> 4) << 3) + (lane & 7);
    const int bkc = ((lane >> 3) & 1) * 8;
    const uint32_t b_hi0 = smem_u32(Whi + (bnr * 520 + bkc));
    const uint32_t b_hi1 = smem_u32(Whi + ((16 + bnr) * 520 + bkc));
    const uint32_t b_lo0 = smem_u32(Wlo + (bnr * 520 + bkc));
    const uint32_t b_lo1 = smem_u32(Wlo + ((16 + bnr) * 520 + bkc));

    unsigned* myflag = &g_flags[bx * 32];
    unsigned* pollflag = &g_flags[tid * 32];   // 128 threads poll 128 CTAs
    __syncthreads();

    for (int t = 0; t < TT; t++) {
        float d[4][4];
#pragma unroll
        for (int g = 0; g < 4; g++)
#pragma unroll
            for (int q = 0; q < 4; q++) d[g][q] = 0.f;

        if (t > 0) {
            // stage h(t-1) for our 64 batches, split to bf16 hi/lo
            const float* hsrc = hs + ((size_t)(t - 1) * BB + cb * 64) * HH;
#pragma unroll 4
            for (int i = tid; i < 8192; i += 128) {
                int rr = i >> 7, c4 = (i & 127) * 4;
                float4 v = __ldcg((const float4*)(hsrc + (size_t)rr * HH + c4));
                __nv_bfloat162 h0, h1, l0, l1;
                split4(v, h0, h1, l0, l1);
                *(__nv_bfloat162*)(Hhi + rr * 520 + c4) = h0;
                *(__nv_bfloat162*)(Hhi + rr * 520 + c4 + 2) = h1;
                *(__nv_bfloat162*)(Hlo + rr * 520 + c4) = l0;
                *(__nv_bfloat162*)(Hlo + rr * 520 + c4 + 2) = l1;
            }
            __syncthreads();

#pragma unroll 2
            for (int kk = 0; kk < 512; kk += 16) {
                const uint32_t kb = kk * 2;   // bytes
                uint32_t ah[4], al[4], bh0[4], bh1[4], bl0[4], bl1[4];
                ldsm_x4(ah, a_hi + kb);
                ldsm_x4(al, a_lo + kb);
                ldsm_x4(bh0, b_hi0 + kb);
                ldsm_x4(bh1, b_hi1 + kb);
                ldsm_x4(bl0, b_lo0 + kb);
                ldsm_x4(bl1, b_lo1 + kb);
                // gates 0,1 from bh0/bl0; gates 2,3 from bh1/bl1
                mma_bf16(d[0], ah, bh0 + 0);
                mma_bf16(d[1], ah, bh0 + 2);
                mma_bf16(d[2], ah, bh1 + 0);
                mma_bf16(d[3], ah, bh1 + 2);
                mma_bf16(d[0], al, bh0 + 0);
                mma_bf16(d[1], al, bh0 + 2);
                mma_bf16(d[2], al, bh1 + 0);
                mma_bf16(d[3], al, bh1 + 2);
                mma_bf16(d[0], ah, bl0 + 0);
                mma_bf16(d[1], ah, bl0 + 2);
                mma_bf16(d[2], ah, bl1 + 0);
                mma_bf16(d[3], ah, bl1 + 2);
            }
        }

        // gates + state update for the 4 (b,col) states; D frag q = state
        float* hdst = hs + (size_t)t * BB * HH;
#pragma unroll
        for (int s = 0; s < 4; s++) {
            float gi = d[0][s] + xv[s][0];
            float gf = d[1][s] + xv[s][1];
            float gG = d[2][s] + xv[s][2];
            float go = d[3][s] + xv[s][3];
            float si = 1.f / (1.f + expf(-gi));
            float sf = 1.f / (1.f + expf(-gf));
            float so = 1.f / (1.f + expf(-go));
            cst[s] = sf * cst[s] + si * tanhf(gG);
            float h = so * tanhf(cst[s]);
            int b = r0 + (s >> 1) * 8, col = c0 + (s & 1);
            __stcg(hdst + (size_t)b * HH + col, h);
        }

        // prefetch next step's xg (independent)
        if (t + 1 < TT) {
            const float* xn = xg + (size_t)(t + 1) * G4 * BB;
#pragma unroll
            for (int s = 0; s < 4; s++) {
                int b = r0 + (s >> 1) * 8, col = c0 + (s & 1);
#pragma unroll
                for (int g = 0; g < 4; g++)
                    xv[s][g] = __ldcg(xn + (size_t)(g * HH + col) * BB + b);
            }
        }

        // fence-free release/acquire grid barrier
        __syncthreads();
        if (tid == 0) {
            asm volatile("st.release.gpu.u32 [%0], %1;"
                         :: "l"(myflag), "r"((unsigned)(t + 1)) : "memory");
        }
        {
            unsigned v;
            do {
                asm volatile("ld.acquire.gpu.u32 %0, [%1];"
                             : "=r"(v) : "l"(pollflag) : "memory");
            } while (v < (unsigned)(t + 1));
        }
        __syncthreads();
    }
}

// ---- r[b][g] = h_last[b][:] @ U1[g][512:1024] ----
__global__ __launch_bounds__(256) void k_r(
    const float* __restrict__ hs, const float* __restrict__ U1, float* __restrict__ r)
{
    __shared__ float hl[512];
    const int b = blockIdx.x, tid = threadIdx.x;
    for (int i = tid; i < 512; i += 256)
        hl[i] = hs[((size_t)(TT - 1) * BB + b) * HH + i];
    __syncthreads();
    for (int g = tid; g < 512; g += 256) {
        const float* up = U1 + (size_t)g * 1024 + 512;
        float acc = 0.f;
        for (int k = 0; k < 512; k += 4) {
            float4 u = *(const float4*)(up + k);
            acc += hl[k] * u.x + hl[k+1] * u.y + hl[k+2] * u.z + hl[k+3] * u.w;
        }
        r[(size_t)b * HH + g] = acc;
    }
}

// ---- e[m] += sum_g tanh(hs@U1a + x@U2 + r) * Ve[g] ----
__global__ __launch_bounds__(256, 2) void k_e(
    const float* __restrict__ hs, const float* __restrict__ x,
    const float* __restrict__ U1, const float* __restrict__ U2,
    const float* __restrict__ r, const float* __restrict__ Ve,
    float* __restrict__ e)
{
    __shared__ float As[2][8][132];
    __shared__ float Bs[2][8][132];
    const int tid = threadIdx.x;
    const int tx = tid & 15, ty = tid >> 4;
    const int mBase = blockIdx.y * 128, nBase = blockIdx.x * 128;
    const int lr = tid >> 1, lk = (tid & 1) * 4;
    const int m = mBase + lr;
    const float* aptrs[2] = { hs + (size_t)m * HH + lk,
                              x + ((size_t)(m & 127) * TT + (m >> 7)) * HH + lk };
    const float* bptrs[2] = { U1 + (size_t)(nBase + lr) * 1024 + lk,
                              U2 + (size_t)(nBase + lr) * 512 + lk };

    ull acc[8][4];
#pragma unroll
    for (int i = 0; i < 8; i++)
#pragma unroll
        for (int j = 0; j < 4; j++) acc[i][j] = 0ull;

    {
        float4 av = *(const float4*)aptrs[0];
        float4 bv = *(const float4*)bptrs[0];
        As[0][lk+0][lr]=av.x; As[0][lk+1][lr]=av.y; As[0][lk+2][lr]=av.z; As[0][lk+3][lr]=av.w;
        Bs[0][lk+0][lr]=bv.x; Bs[0][lk+1][lr]=bv.y; Bs[0][lk+2][lr]=bv.z; Bs[0][lk+3][lr]=bv.w;
    }
    __syncthreads();
    int buf = 0;

    for (int ph = 0; ph < 2; ph++) {
        const float* ap = aptrs[ph];
        const float* bp_ = bptrs[ph];
        for (int k0 = 0; k0 < HH; k0 += 8) {
            const bool last = (ph == 1) && (k0 + 8 >= HH);
            float4 av2, bv2;
            if (!last) {
                const float* an = (k0 + 8 < HH) ? ap + k0 + 8 : aptrs[1];
                const float* bn = (k0 + 8 < HH) ? bp_ + k0 + 8 : bptrs[1];
                av2 = *(const float4*)an;
                bv2 = *(const float4*)bn;
            }
#pragma unroll
            for (int k = 0; k < 8; k++) {
                float4 a0 = *(const float4*)&As[buf][k][ty * 8];
                float4 a1 = *(const float4*)&As[buf][k][ty * 8 + 4];
                ulonglong2 b0 = *(const ulonglong2*)&Bs[buf][k][tx * 8];
                ulonglong2 b1 = *(const ulonglong2*)&Bs[buf][k][tx * 8 + 4];
                float af[8] = {a0.x, a0.y, a0.z, a0.w, a1.x, a1.y, a1.z, a1.w};
                ull bp2[4] = {b0.x, b0.y, b1.x, b1.y};
#pragma unroll
                for (int i = 0; i < 8; i++) {
                    ull apk = pack2(af[i], af[i]);
#pragma unroll
                    for (int j = 0; j < 4; j++) acc[i][j] = fma2(apk, bp2[j], acc[i][j]);
                }
            }
            if (!last) {
                int nb = buf ^ 1;
                As[nb][lk+0][lr]=av2.x; As[nb][lk+1][lr]=av2.y; As[nb][lk+2][lr]=av2.z; As[nb][lk+3][lr]=av2.w;
                Bs[nb][lk+0][lr]=bv2.x; Bs[nb][lk+1][lr]=bv2.y; Bs[nb][lk+2][lr]=bv2.z; Bs[nb][lk+3][lr]=bv2.w;
            }
            __syncthreads();
            buf ^= 1;
        }
    }

    const int gc = nBase + tx * 8;
    float ve[8];
#pragma unroll
    for (int j = 0; j < 8; j++) ve[j] = Ve[gc + j];
#pragma unroll
    for (int i = 0; i < 8; i++) {
        const int brow = ty * 8 + i;
        const float* rr = r + (size_t)brow * HH + gc;
        float si = 0.f; float2 v;
        v = unpack2(acc[i][0]); si += tanhf(v.x + rr[0]) * ve[0] + tanhf(v.y + rr[1]) * ve[1];
        v = unpack2(acc[i][1]); si += tanhf(v.x + rr[2]) * ve[2] + tanhf(v.y + rr[3]) * ve[3];
        v = unpack2(acc[i][2]); si += tanhf(v.x + rr[4]) * ve[4] + tanhf(v.y + rr[5]) * ve[5];
        v = unpack2(acc[i][3]); si += tanhf(v.x + rr[6]) * ve[6] + tanhf(v.y + rr[7]) * ve[7];
#pragma unroll
        for (int o = 8; o >= 1; o >>= 1)
            si += __shfl_xor_sync(0xffffffffu, si, o, 16);
        if (tx == 0) atomicAdd(&e[mBase + ty * 8 + i], si);
    }
}

// ---- softmax over t, context, output head ----
__global__ __launch_bounds__(256) void k_final(
    const float* __restrict__ hs, const float* __restrict__ e,
    const float* __restrict__ Wout, const float* __restrict__ bout,
    float* __restrict__ out)
{
    __shared__ float al[512];
    __shared__ float red[256];
    const int b = blockIdx.x, tid = threadIdx.x;

    float ev0 = e[(size_t)tid * BB + b];
    float ev1 = e[(size_t)(tid + 256) * BB + b];

    red[tid] = fmaxf(ev0, ev1);
    __syncthreads();
    for (int s = 128; s > 0; s >>= 1) {
        if (tid < s) red[tid] = fmaxf(red[tid], red[tid + s]);
        __syncthreads();
    }
    float mx = red[0];
    __syncthreads();
    float x0 = expf(ev0 - mx), x1 = expf(ev1 - mx);
    red[tid] = x0 + x1;
    __syncthreads();
    for (int s = 128; s > 0; s >>= 1) {
        if (tid < s) red[tid] += red[tid + s];
        __syncthreads();
    }
    float inv = 1.f / red[0];
    al[tid] = x0 * inv;
    al[tid + 256] = x1 * inv;
    __syncthreads();

    float ctx0 = 0.f, ctx1 = 0.f;
    for (int t = 0; t < TT; t++) {
        float a = al[t];
        const float* hp = hs + ((size_t)t * BB + b) * HH;
        ctx0 += a * hp[tid];
        ctx1 += a * hp[tid + 256];
    }

    float p0 = ctx0 * Wout[tid] + ctx1 * Wout[tid + 256];
    float p1 = ctx0 * Wout[512 + tid] + ctx1 * Wout[512 + tid + 256];
    red[tid] = p0;
    __syncthreads();
    for (int s = 128; s > 0; s >>= 1) {
        if (tid < s) red[tid] += red[tid + s];
        __syncthreads();
    }
    float mu = red[0] + bout[0];
    __syncthreads();
    red[tid] = p1;
    __syncthreads();
    for (int s = 128; s > 0; s >>= 1) {
        if (tid < s) red[tid] += red[tid + s];
        __syncthreads();
    }
    if (tid == 0) {
        float pv = red[0] + bout[1];
        float sp = (pv > 20.f) ? pv : log1pf(expf(pv));
        out[b] = mu;
        out[BB + b] = sp + 1e-5f;
    }
}

extern "C" void kernel_launch(void* const* d_in, const int* in_sizes, int n_in,
                              void* d_out, int out_size) {
    const float* x    = (const float*)d_in[0];
    const float* Wih  = (const float*)d_in[1];
    const float* Whh  = (const float*)d_in[2];
    const float* bih  = (const float*)d_in[3];
    const float* bhh  = (const float*)d_in[4];
    const float* Ve   = (const float*)d_in[5];
    const float* U1   = (const float*)d_in[6];
    const float* U2   = (const float*)d_in[7];
    const float* Wout = (const float*)d_in[8];
    const float* bout = (const float*)d_in[9];
    float* out = (float*)d_out;

    float *xg, *hs, *r, *e;
    __nv_bfloat16 *xh, *xl, *wh, *wl;
    cudaGetSymbolAddress((void**)&xg, g_xg);
    cudaGetSymbolAddress((void**)&hs, g_hs);
    cudaGetSymbolAddress((void**)&r,  g_r);
    cudaGetSymbolAddress((void**)&e,  g_e);
    cudaGetSymbolAddress((void**)&xh, g_xh);
    cudaGetSymbolAddress((void**)&xl, g_xl);
    cudaGetSymbolAddress((void**)&wh, g_wh);
    cudaGetSymbolAddress((void**)&wl, g_wl);

    const int xg_smem   = 4 * 128 * 72 * 2;                    // 73728 B
    const int lstm_smem = (2 * 64 * 520 + 2 * 32 * 520) * 2;   // 199680 B
    cudaFuncSetAttribute(k_xg_mma,   cudaFuncAttributeMaxDynamicSharedMemorySize, xg_smem);
    cudaFuncSetAttribute(k_lstm_mma, cudaFuncAttributeMaxDynamicSharedMemorySize, lstm_smem);

    k_init<<<(TT * BB + 255) / 256, 256>>>(e);
    k_split<<<BB * TT + G4, 128>>>(x, Wih, xh, xl, wh, wl);
    {
        dim3 g(G4 / 128, TT);
        k_xg_mma<<<g, 256, xg_smem>>>(xh, xl, wh, wl, bih, bhh, xg);
    }
    k_lstm_mma<<<128, 128, lstm_smem>>>(Whh, xg, hs);
    k_r<<<BB, 256>>>(hs, U1, r);
    {
        dim3 g(HH / 128, (TT * BB) / 128);
        k_e<<<g, 256>>>(hs, x, U1, U2, r, Ve, e);
    }
    k_final<<<BB, 256>>>(hs, e, Wout, bout, out);
}